// round 9
// baseline (speedup 1.0000x reference)
#include <cuda_runtime.h>
#include <cstdint>

// Problem constants
#define BB 32
#define II 2048
#define OO 32
#define CC 16
#define UU 32
#define KTOT (II*CC)        // 32768

// D[1024(m=o*32+u), 32(n=b)] = W^T * X^T
#define MT  16              // m-tiles of 64 rows (2 o x 32 u)
#define KS  64              // k-splits
#define KC  32              // k per chunk (2 i's)
#define NCH (KTOT/(KS*KC))  // 16 chunks per block
#define NSEG 16             // reduce stage-1 segments

#define ISTRIDE (OO*CC*UU)  // floats between consecutive i in w

// Scratch: partials [mt][ks][m_local(64)][b(32)] = 8MB, stage1 = 2MB
__device__ float g_spart[(size_t)MT * KS * 64 * BB];
__device__ float g_s1[(size_t)OO * NSEG * UU * BB];

// ---------------------------------------------------------------------------
__device__ __forceinline__ uint32_t smem_u32(const void* p) {
    uint32_t a;
    asm("{ .reg .u64 t; cvta.to.shared.u64 t, %1; cvt.u32.u64 %0, t; }"
        : "=r"(a) : "l"(p));
    return a;
}
// pack two f32 -> bf16x2, lo in bits[15:0]
__device__ __forceinline__ uint32_t pack_bf16(float lo, float hi) {
    uint32_t r;
    asm("cvt.rn.bf16x2.f32 %0, %1, %2;" : "=r"(r) : "f"(hi), "f"(lo));
    return r;
}
__device__ __forceinline__ void ldsm_x4(uint32_t* r, uint32_t addr) {
    asm volatile("ldmatrix.sync.aligned.m8n8.x4.shared.b16 {%0,%1,%2,%3}, [%4];"
                 : "=r"(r[0]), "=r"(r[1]), "=r"(r[2]), "=r"(r[3]) : "r"(addr));
}
__device__ __forceinline__ void ldsm_x4_t(uint32_t* r, uint32_t addr) {
    asm volatile("ldmatrix.sync.aligned.m8n8.x4.trans.shared.b16 {%0,%1,%2,%3}, [%4];"
                 : "=r"(r[0]), "=r"(r[1]), "=r"(r[2]), "=r"(r[3]) : "r"(addr));
}
__device__ __forceinline__ void mma_bf16(float* d, const uint32_t* a,
                                         uint32_t b0, uint32_t b1) {
    asm volatile(
        "mma.sync.aligned.m16n8k16.row.col.f32.bf16.bf16.f32 "
        "{%0,%1,%2,%3}, {%4,%5,%6,%7}, {%8,%9}, {%0,%1,%2,%3};"
        : "+f"(d[0]), "+f"(d[1]), "+f"(d[2]), "+f"(d[3])
        : "r"(a[0]), "r"(a[1]), "r"(a[2]), "r"(a[3]), "r"(b0), "r"(b1));
}

// B (64B rows): 16B group j of row r -> r*64 + ((j ^ ((r>>1)&3))<<4)
__device__ __forceinline__ uint32_t sw64(int row, int grp) {
    return (uint32_t)(row * 64 + ((grp ^ ((row >> 1) & 3)) << 4));
}
// A ([k(32)][m(64)], 128B rows): 16B m-group g of k-row r -> r*128 + ((g^(r&7))<<4)
__device__ __forceinline__ uint32_t swA(int krow, int mgrp) {
    return (uint32_t)(krow * 128 + ((mgrp ^ (krow & 7)) << 4));
}

// ---------------------------------------------------------------------------
// GEMM: grid (MT, KS), 64 threads (2 warps), 8 CTAs/SM.
// Warp w owns o = mt*2 + w. A smem [k32][m64] bf16 hi/lo (warp-private halves),
// B smem [b32][k32]. Prefetch issued BEFORE the (2-warp) barrier.
// ---------------------------------------------------------------------------
__global__ void __launch_bounds__(64, 8) gemm_tc(const float* __restrict__ w,
                                                 const float* __restrict__ x) {
    __shared__ __align__(128) uint8_t A_HI[2][32 * 128];
    __shared__ __align__(128) uint8_t A_LO[2][32 * 128];
    __shared__ __align__(128) uint8_t B_HI[2][32 * 64];
    __shared__ __align__(128) uint8_t B_LO[2][32 * 64];

    const int mt   = blockIdx.x;
    const int ks   = blockIdx.y;
    const int tid  = threadIdx.x;
    const int wd   = tid >> 5;        // warp 0/1
    const int lane = tid & 31;

    // A-convert mapping: thread covers k-row r (all 32 m of its half)
    const int r     = tid & 31;       // k-row (il = r>>4, c = r&15)
    const int mhalf = tid >> 5;       // m 0..31 (warp0's o) or 32..63 (warp1's)
    const int oA    = mt * 2 + mhalf;
    const float* const wbase =
        w + (((size_t)(ks * NCH * 2 + (r >> 4)) * OO + oA) * CC + (r & 15)) * UU;

    // B-convert mapping: thread covers (b = tid>>1, k-half = tid&1)
    const int xb = tid >> 1, xh = tid & 1;
    const float4* const xbase =
        (const float4*)(x + (size_t)xb * KTOT + ks * (NCH * KC) + xh * 16);

    float4 va[8];
    float4 vb[4];

    // prefetch chunk 0: A = thread's 128B k-row slice, B = 64B x slice
#pragma unroll
    for (int j = 0; j < 8; j++) va[j] = ((const float4*)wbase)[j];
#pragma unroll
    for (int f = 0; f < 4; f++) vb[f] = xbase[f];

    float acc[2][4][4];
#pragma unroll
    for (int a = 0; a < 2; a++)
#pragma unroll
        for (int b = 0; b < 4; b++)
#pragma unroll
            for (int c = 0; c < 4; c++) acc[a][b][c] = 0.f;

    for (int t = 0; t < NCH; t++) {
        const int p = t & 1;

        // ---- convert A chunk t: 8 float4 along m -> 4 x (uint4 hi + uint4 lo)
#pragma unroll
        for (int j = 0; j < 4; j++) {
            float4 v0 = va[2 * j], v1 = va[2 * j + 1];
            uint32_t h0 = pack_bf16(v0.x, v0.y);
            uint32_t h1 = pack_bf16(v0.z, v0.w);
            uint32_t h2 = pack_bf16(v1.x, v1.y);
            uint32_t h3 = pack_bf16(v1.z, v1.w);
            float r0 = v0.x - __uint_as_float(h0 << 16);
            float r1 = v0.y - __uint_as_float(h0 & 0xffff0000u);
            float r2 = v0.z - __uint_as_float(h1 << 16);
            float r3 = v0.w - __uint_as_float(h1 & 0xffff0000u);
            float r4 = v1.x - __uint_as_float(h2 << 16);
            float r5 = v1.y - __uint_as_float(h2 & 0xffff0000u);
            float r6 = v1.z - __uint_as_float(h3 << 16);
            float r7 = v1.w - __uint_as_float(h3 & 0xffff0000u);
            uint32_t l0 = pack_bf16(r0, r1);
            uint32_t l1 = pack_bf16(r2, r3);
            uint32_t l2 = pack_bf16(r4, r5);
            uint32_t l3 = pack_bf16(r6, r7);
            const int g = mhalf * 4 + j;           // m-octet index 0..7
            const uint32_t off = swA(r, g);
            *(uint4*)(A_HI[p] + off) = make_uint4(h0, h1, h2, h3);
            *(uint4*)(A_LO[p] + off) = make_uint4(l0, l1, l2, l3);
        }
        // ---- convert B chunk t: 16 k-floats for (b=xb, half xh)
        {
            float v[16] = {vb[0].x, vb[0].y, vb[0].z, vb[0].w,
                           vb[1].x, vb[1].y, vb[1].z, vb[1].w,
                           vb[2].x, vb[2].y, vb[2].z, vb[2].w,
                           vb[3].x, vb[3].y, vb[3].z, vb[3].w};
            uint32_t h[8], l[8];
#pragma unroll
            for (int q = 0; q < 8; q++) {
                h[q] = pack_bf16(v[2 * q], v[2 * q + 1]);
                float r0 = v[2 * q]     - __uint_as_float(h[q] << 16);
                float r1 = v[2 * q + 1] - __uint_as_float(h[q] & 0xffff0000u);
                l[q] = pack_bf16(r0, r1);
            }
            const int g0 = xh * 2;
            *(uint4*)(B_HI[p] + sw64(xb, g0))     = make_uint4(h[0], h[1], h[2], h[3]);
            *(uint4*)(B_HI[p] + sw64(xb, g0 + 1)) = make_uint4(h[4], h[5], h[6], h[7]);
            *(uint4*)(B_LO[p] + sw64(xb, g0))     = make_uint4(l[0], l[1], l[2], l[3]);
            *(uint4*)(B_LO[p] + sw64(xb, g0 + 1)) = make_uint4(l[4], l[5], l[6], l[7]);
        }

        // ---- prefetch chunk t+1 BEFORE the barrier (overlap LDG w/ bar+MMA)
        if (t + 1 < NCH) {
            const float4* wp =
                (const float4*)(wbase + (size_t)((t + 1) * 2) * ISTRIDE);
#pragma unroll
            for (int j = 0; j < 8; j++) va[j] = wp[j];
            const float4* xp = xbase + (t + 1) * (KC / 4);
#pragma unroll
            for (int f = 0; f < 4; f++) vb[f] = xp[f];
        }

        __syncthreads();   // 2-warp barrier: buf[p] ready

        // ---- MMA: 2 k-tiles of 16; alo reuses ahi registers
        const uint32_t aHi = smem_u32(A_HI[p]), aLo = smem_u32(A_LO[p]);
        const uint32_t bHi = smem_u32(B_HI[p]), bLo = smem_u32(B_LO[p]);

        const int a_koff = ((lane >> 4) & 1) * 8 + (lane & 7);
        const int a_moff = ((lane >> 3) & 1) * 8;
        const int bn     = (lane & 7) + ((lane >> 4) & 1) * 8;
#pragma unroll
        for (int kt = 0; kt < 2; kt++) {
            uint32_t af[2][4], bhiR[2][4], bloR[2][4];

            const int krow = kt * 16 + a_koff;
            const int bkg  = 2 * kt + ((lane >> 3) & 1);
#pragma unroll
            for (int m2 = 0; m2 < 2; m2++) {
                const int mcol = wd * 32 + m2 * 16 + a_moff;
                ldsm_x4_t(af[m2], aHi + swA(krow, mcol >> 3));
            }
#pragma unroll
            for (int g2 = 0; g2 < 2; g2++) {
                const uint32_t off = sw64(g2 * 16 + bn, bkg);
                ldsm_x4(bhiR[g2], bHi + off);
                ldsm_x4(bloR[g2], bLo + off);
            }
            // A_hi x B_hi and A_hi x B_lo
#pragma unroll
            for (int m2 = 0; m2 < 2; m2++)
#pragma unroll
                for (int nt = 0; nt < 4; nt++) {
                    mma_bf16(acc[m2][nt], af[m2],
                             bhiR[nt >> 1][(nt & 1) * 2], bhiR[nt >> 1][(nt & 1) * 2 + 1]);
                    mma_bf16(acc[m2][nt], af[m2],
                             bloR[nt >> 1][(nt & 1) * 2], bloR[nt >> 1][(nt & 1) * 2 + 1]);
                }
            // reload af with A_lo, then A_lo x B_hi
#pragma unroll
            for (int m2 = 0; m2 < 2; m2++) {
                const int mcol = wd * 32 + m2 * 16 + a_moff;
                ldsm_x4_t(af[m2], aLo + swA(krow, mcol >> 3));
            }
#pragma unroll
            for (int m2 = 0; m2 < 2; m2++)
#pragma unroll
                for (int nt = 0; nt < 4; nt++)
                    mma_bf16(acc[m2][nt], af[m2],
                             bhiR[nt >> 1][(nt & 1) * 2], bhiR[nt >> 1][(nt & 1) * 2 + 1]);
        }
        // buf[p] reused at t+2: all warps passed sync(t+1) => MMA(t) complete.
    }

    // ---- epilogue: D fragments -> g_spart[(mt*KS+ks)][m_local(64)][b]
    float* outp = g_spart + ((size_t)(mt * KS + ks)) * (64 * BB);
#pragma unroll
    for (int m2 = 0; m2 < 2; m2++)
#pragma unroll
        for (int nt = 0; nt < 4; nt++) {
            const int r0 = wd * 32 + m2 * 16 + (lane >> 2);
            const int c  = nt * 8 + 2 * (lane & 3);
            *(float2*)(outp + (size_t)r0 * BB + c) =
                make_float2(acc[m2][nt][0], acc[m2][nt][1]);
            *(float2*)(outp + (size_t)(r0 + 8) * BB + c) =
                make_float2(acc[m2][nt][2], acc[m2][nt][3]);
        }
}

// ---------------------------------------------------------------------------
// Reduce stage 1: grid (OO, NSEG), 256 threads, float4. Sums KS/NSEG=4 splits.
// g_spart m_local = (o&1)*32 + u, mt = o>>1.
// ---------------------------------------------------------------------------
__global__ void __launch_bounds__(256) reduce1() {
    const int o = blockIdx.x, seg = blockIdx.y;
    const int t = threadIdx.x;
    const int uu2 = t >> 3, q = t & 7;
    const int mt = o >> 1;
    const int mrow = (o & 1) * 32 + uu2;

    const float4* p = (const float4*)(g_spart +
        (((size_t)mt * KS + seg * (KS / NSEG)) * 64 + mrow) * BB) + q;
    float4 s = make_float4(0.f, 0.f, 0.f, 0.f);
#pragma unroll
    for (int k = 0; k < KS / NSEG; k++) {
        float4 v = p[(size_t)k * (64 * BB / 4)];
        s.x += v.x; s.y += v.y; s.z += v.z; s.w += v.w;
    }
    *((float4*)(g_s1 + (((size_t)o * NSEG + seg) * UU + uu2) * BB) + q) = s;
}

// ---------------------------------------------------------------------------
// Reduce stage 2 + squash: grid = OO, 256 threads.
// ---------------------------------------------------------------------------
__global__ void __launch_bounds__(256) reduce2(float* __restrict__ out) {
    const int o = blockIdx.x;
    const int t = threadIdx.x;
    const int uu2 = t >> 3, q = t & 7;

    __shared__ float sblk[UU * 36];    // [u][b], pad 36
    __shared__ float scale_s[BB];

    float4 s = make_float4(0.f, 0.f, 0.f, 0.f);
#pragma unroll
    for (int seg = 0; seg < NSEG; seg++) {
        float4 v = *((const float4*)(g_s1 +
            (((size_t)o * NSEG + seg) * UU + uu2) * BB) + q);
        s.x += v.x; s.y += v.y; s.z += v.z; s.w += v.w;
    }
    sblk[uu2 * 36 + 4 * q + 0] = s.x;
    sblk[uu2 * 36 + 4 * q + 1] = s.y;
    sblk[uu2 * 36 + 4 * q + 2] = s.z;
    sblk[uu2 * 36 + 4 * q + 3] = s.w;
    __syncthreads();

    if (t < BB) {
        float nsq = 0.f;
#pragma unroll
        for (int uv = 0; uv < UU; uv++) {
            float sv = sblk[uv * 36 + t];
            nsq += sv * sv;
        }
        scale_s[t] = sqrtf(nsq) / (1.0f + nsq);
    }
    __syncthreads();

#pragma unroll
    for (int r = 0; r < 4; r++) {
        const int gid = t + 256 * r;           // b2*32 + u2
        const int b2 = gid >> 5, u2 = gid & 31;
        out[(size_t)b2 * (OO * UU) + o * UU + u2] =
            sblk[u2 * 36 + b2] * scale_s[b2];
    }
}

// ---------------------------------------------------------------------------
extern "C" void kernel_launch(void* const* d_in, const int* in_sizes, int n_in,
                              void* d_out, int out_size) {
    const float* x = (const float*)d_in[0];
    const float* w = (const float*)d_in[1];
    if (n_in >= 2 && in_sizes[0] > in_sizes[1]) {   // guard input ordering
        x = (const float*)d_in[1];
        w = (const float*)d_in[0];
    }

    gemm_tc<<<dim3(MT, KS), 64>>>(w, x);
    reduce1<<<dim3(OO, NSEG), 256>>>();
    reduce2<<<OO, 256>>>((float*)d_out);
}

// round 10
// speedup vs baseline: 1.6944x; 1.6944x over previous
#include <cuda_runtime.h>
#include <cstdint>

// Problem constants
#define BB 32
#define II 2048
#define OO 32
#define CC 16
#define UU 32
#define KTOT (II*CC)        // 32768

// D[1024(m=o*32+u), 32(n=b)] = W^T * X^T, one warp per (o, k-split)
#define KS  64              // k-splits (512 k each)
#define NCH 16              // chunks per warp (32 k = 2 i's per chunk)
#define NSEG 16             // reduce stage-1 segments

#define ISTRIDE (OO*CC*UU)  // floats between consecutive i in w (16384)

// Scratch: partials [o(32)][ks(64)][u(32)][b(32)] = 8MB, stage1 = 2MB
__device__ float g_spart[(size_t)OO * KS * 32 * BB];
__device__ float g_s1[(size_t)OO * NSEG * UU * BB];

// ---------------------------------------------------------------------------
// pack two f32 -> bf16x2, first arg in bits[15:0]
__device__ __forceinline__ uint32_t pack_bf16(float lo, float hi) {
    uint32_t r;
    asm("cvt.rn.bf16x2.f32 %0, %1, %2;" : "=r"(r) : "f"(hi), "f"(lo));
    return r;
}
__device__ __forceinline__ void mma_bf16(float* d, const uint32_t* a,
                                         uint32_t b0, uint32_t b1) {
    asm volatile(
        "mma.sync.aligned.m16n8k16.row.col.f32.bf16.bf16.f32 "
        "{%0,%1,%2,%3}, {%4,%5,%6,%7}, {%8,%9}, {%0,%1,%2,%3};"
        : "+f"(d[0]), "+f"(d[1]), "+f"(d[2]), "+f"(d[3])
        : "r"(a[0]), "r"(a[1]), "r"(a[2]), "r"(a[3]), "r"(b0), "r"(b1));
}

// ---------------------------------------------------------------------------
// GEMM: grid (32, 64) single-warp CTAs. No smem, no barriers, no ldmatrix.
// Warp = (o, ks). Per chunk (k=32): 16 LDG.64 (B) + 32 LDG.32 (A) straight
// into mma fragments, hi/lo bf16 split in registers, 48 HMMA.
// Fragment map (m16n8k16): g=lane>>2, t2=2*(lane&3);
//   a0=(m:g, k:t2..t2+1) a1=(g+8, t2) a2=(g, t2+8) a3=(g+8, t2+8)
//   b0=(k:t2..t2+1, n:g) b1=(k:t2+8.., n:g);  d0,d1=(g, t2|+1) d2,d3=(g+8, ..)
// ---------------------------------------------------------------------------
__global__ void __launch_bounds__(32, 16) gemm_tc(const float* __restrict__ w,
                                                  const float* __restrict__ x) {
    const int o    = blockIdx.x;
    const int ks   = blockIdx.y;
    const int lane = threadIdx.x;
    const int g    = lane >> 2;
    const int t2   = (lane & 3) * 2;

    // A: w[i][o][c][u]; this lane reads c = t2 (+1,+8,+9), u = g (+8, +16, +24)
    const float* wb =
        w + (((size_t)(ks * (NCH * 2)) * OO + o) * CC + t2) * UU + g;
    // B: x[b][k]; this lane reads b = g (+8,+16,+24), k = t2 pairs
    const float* xb = x + (size_t)g * KTOT + ks * (NCH * 32) + t2;

    float acc[2][4][4];
#pragma unroll
    for (int a = 0; a < 2; a++)
#pragma unroll
        for (int b = 0; b < 4; b++)
#pragma unroll
            for (int c = 0; c < 4; c++) acc[a][b][c] = 0.f;

    for (int t = 0; t < NCH; t++) {
        // ---- issue ALL loads for this chunk back-to-back (MLP ~ 48) ----
        float2 br[4][2][2];                    // [nt][kt][h]
#pragma unroll
        for (int nt = 0; nt < 4; nt++)
#pragma unroll
            for (int kt = 0; kt < 2; kt++)
#pragma unroll
                for (int h = 0; h < 2; h++)
                    br[nt][kt][h] = *(const float2*)
                        (xb + (size_t)nt * (8 * KTOT) + kt * 16 + h * 8);

        float ar[2][2][8];                     // [kt][m2][elem]
#pragma unroll
        for (int kt = 0; kt < 2; kt++)
#pragma unroll
            for (int m2 = 0; m2 < 2; m2++) {
                const float* p = wb + (size_t)kt * ISTRIDE + m2 * 16;
                ar[kt][m2][0] = p[0];           // (c=t2,   u0)
                ar[kt][m2][1] = p[UU];          // (c=t2+1, u0)
                ar[kt][m2][2] = p[8];           // (c=t2,   u0+8)
                ar[kt][m2][3] = p[UU + 8];
                ar[kt][m2][4] = p[8 * UU];      // (c=t2+8, u0)
                ar[kt][m2][5] = p[9 * UU];
                ar[kt][m2][6] = p[8 * UU + 8];
                ar[kt][m2][7] = p[9 * UU + 8];
            }

        // ---- convert B to hi/lo fragments ----
        uint32_t bh[4][2][2], bl[4][2][2];
#pragma unroll
        for (int nt = 0; nt < 4; nt++)
#pragma unroll
            for (int kt = 0; kt < 2; kt++)
#pragma unroll
                for (int h = 0; h < 2; h++) {
                    float2 v = br[nt][kt][h];
                    uint32_t hi = pack_bf16(v.x, v.y);
                    float r0 = v.x - __uint_as_float(hi << 16);
                    float r1 = v.y - __uint_as_float(hi & 0xffff0000u);
                    bh[nt][kt][h] = hi;
                    bl[nt][kt][h] = pack_bf16(r0, r1);
                }

        // ---- per (kt, m2): convert A fragment, then 12 MMAs ----
#pragma unroll
        for (int kt = 0; kt < 2; kt++)
#pragma unroll
            for (int m2 = 0; m2 < 2; m2++) {
                uint32_t ah[4], al[4];
#pragma unroll
                for (int q = 0; q < 4; q++) {
                    float v0 = ar[kt][m2][2 * q], v1 = ar[kt][m2][2 * q + 1];
                    uint32_t hi = pack_bf16(v0, v1);
                    float r0 = v0 - __uint_as_float(hi << 16);
                    float r1 = v1 - __uint_as_float(hi & 0xffff0000u);
                    ah[q] = hi;
                    al[q] = pack_bf16(r0, r1);
                }
#pragma unroll
                for (int nt = 0; nt < 4; nt++) {
                    const uint32_t b0h = bh[nt][kt][0], b1h = bh[nt][kt][1];
                    mma_bf16(acc[m2][nt], ah, b0h, b1h);
                    mma_bf16(acc[m2][nt], al, b0h, b1h);
                    mma_bf16(acc[m2][nt], ah, bl[nt][kt][0], bl[nt][kt][1]);
                }
            }

        wb += 2 * ISTRIDE;   // next 2 i's
        xb += 32;            // next 32 k
    }

    // ---- epilogue: D fragments -> g_spart[o][ks][u][b]
    float* outp = g_spart + ((size_t)o * KS + ks) * (32 * BB);
#pragma unroll
    for (int m2 = 0; m2 < 2; m2++)
#pragma unroll
        for (int nt = 0; nt < 4; nt++) {
            const int row = m2 * 16 + g;
            const int col = nt * 8 + t2;
            *(float2*)(outp + (size_t)row * BB + col) =
                make_float2(acc[m2][nt][0], acc[m2][nt][1]);
            *(float2*)(outp + (size_t)(row + 8) * BB + col) =
                make_float2(acc[m2][nt][2], acc[m2][nt][3]);
        }
}

// ---------------------------------------------------------------------------
// Reduce stage 1: grid (OO, NSEG), 256 threads, float4. Sums KS/NSEG=4 splits.
// ---------------------------------------------------------------------------
__global__ void __launch_bounds__(256) reduce1() {
    const int o = blockIdx.x, seg = blockIdx.y;
    const int t = threadIdx.x;
    const int uu2 = t >> 3, q = t & 7;

    const float4* p = (const float4*)(g_spart +
        (((size_t)o * KS + seg * (KS / NSEG)) * 32 + uu2) * BB) + q;
    float4 s = make_float4(0.f, 0.f, 0.f, 0.f);
#pragma unroll
    for (int k = 0; k < KS / NSEG; k++) {
        float4 v = p[(size_t)k * (32 * BB / 4)];
        s.x += v.x; s.y += v.y; s.z += v.z; s.w += v.w;
    }
    *((float4*)(g_s1 + (((size_t)o * NSEG + seg) * UU + uu2) * BB) + q) = s;
}

// ---------------------------------------------------------------------------
// Reduce stage 2 + squash: grid = OO, 256 threads.
// ---------------------------------------------------------------------------
__global__ void __launch_bounds__(256) reduce2(float* __restrict__ out) {
    const int o = blockIdx.x;
    const int t = threadIdx.x;
    const int uu2 = t >> 3, q = t & 7;

    __shared__ float sblk[UU * 36];    // [u][b], pad 36
    __shared__ float scale_s[BB];

    float4 s = make_float4(0.f, 0.f, 0.f, 0.f);
#pragma unroll
    for (int seg = 0; seg < NSEG; seg++) {
        float4 v = *((const float4*)(g_s1 +
            (((size_t)o * NSEG + seg) * UU + uu2) * BB) + q);
        s.x += v.x; s.y += v.y; s.z += v.z; s.w += v.w;
    }
    sblk[uu2 * 36 + 4 * q + 0] = s.x;
    sblk[uu2 * 36 + 4 * q + 1] = s.y;
    sblk[uu2 * 36 + 4 * q + 2] = s.z;
    sblk[uu2 * 36 + 4 * q + 3] = s.w;
    __syncthreads();

    if (t < BB) {
        float nsq = 0.f;
#pragma unroll
        for (int uv = 0; uv < UU; uv++) {
            float sv = sblk[uv * 36 + t];
            nsq += sv * sv;
        }
        scale_s[t] = sqrtf(nsq) / (1.0f + nsq);
    }
    __syncthreads();

#pragma unroll
    for (int r = 0; r < 4; r++) {
        const int gid = t + 256 * r;           // b2*32 + u2
        const int b2 = gid >> 5, u2 = gid & 31;
        out[(size_t)b2 * (OO * UU) + o * UU + u2] =
            sblk[u2 * 36 + b2] * scale_s[b2];
    }
}

// ---------------------------------------------------------------------------
extern "C" void kernel_launch(void* const* d_in, const int* in_sizes, int n_in,
                              void* d_out, int out_size) {
    const float* x = (const float*)d_in[0];
    const float* w = (const float*)d_in[1];
    if (n_in >= 2 && in_sizes[0] > in_sizes[1]) {   // guard input ordering
        x = (const float*)d_in[1];
        w = (const float*)d_in[0];
    }

    gemm_tc<<<dim3(OO, KS), 32>>>(w, x);
    reduce1<<<dim3(OO, NSEG), 256>>>();
    reduce2<<<OO, 256>>>((float*)d_out);
}

// round 11
// speedup vs baseline: 2.0499x; 1.2098x over previous
#include <cuda_runtime.h>
#include <cstdint>

// Problem constants
#define BB 32
#define II 2048
#define OO 32
#define CC 16
#define UU 32
#define KTOT (II*CC)        // 32768

// D[1024(m=o*32+u), 32(n=b)] = W^T * X^T
#define MT  8               // m-tiles of 128 rows (4 o x 32 u)
#define KS  64              // k-splits
#define KC  32              // k per chunk (2 i's)
#define NCH (KTOT/(KS*KC))  // 16 chunks per block

#define ISTRIDE (OO*CC*UU)  // floats between consecutive i in w

// Scratch: partials [mt][ks][m_local(128)][b(32)] = 8MB
__device__ float g_spart[(size_t)MT * KS * 128 * BB];

// ---------------------------------------------------------------------------
__device__ __forceinline__ uint32_t smem_u32(const void* p) {
    uint32_t a;
    asm("{ .reg .u64 t; cvta.to.shared.u64 t, %1; cvt.u32.u64 %0, t; }"
        : "=r"(a) : "l"(p));
    return a;
}
// pack two f32 -> bf16x2, lo in bits[15:0]
__device__ __forceinline__ uint32_t pack_bf16(float lo, float hi) {
    uint32_t r;
    asm("cvt.rn.bf16x2.f32 %0, %1, %2;" : "=r"(r) : "f"(hi), "f"(lo));
    return r;
}
__device__ __forceinline__ void ldsm_x4(uint32_t* r, uint32_t addr) {
    asm volatile("ldmatrix.sync.aligned.m8n8.x4.shared.b16 {%0,%1,%2,%3}, [%4];"
                 : "=r"(r[0]), "=r"(r[1]), "=r"(r[2]), "=r"(r[3]) : "r"(addr));
}
__device__ __forceinline__ void mma_bf16(float* d, const uint32_t* a,
                                         uint32_t b0, uint32_t b1) {
    asm volatile(
        "mma.sync.aligned.m16n8k16.row.col.f32.bf16.bf16.f32 "
        "{%0,%1,%2,%3}, {%4,%5,%6,%7}, {%8,%9}, {%0,%1,%2,%3};"
        : "+f"(d[0]), "+f"(d[1]), "+f"(d[2]), "+f"(d[3])
        : "r"(a[0]), "r"(a[1]), "r"(a[2]), "r"(a[3]), "r"(b0), "r"(b1));
}

// 64B-row swizzle: 16B group j of row r lives at r*64 + ((j ^ ((r>>1)&3))<<4)
__device__ __forceinline__ uint32_t sw64(int row, int grp) {
    return (uint32_t)(row * 64 + ((grp ^ ((row >> 1) & 3)) << 4));
}

// ---------------------------------------------------------------------------
// GEMM (round-7 validated core): grid (MT, KS), 128 threads, 4 CTAs/SM.
// Only change: prefetch(t+1) hoisted ABOVE the barrier.
// ---------------------------------------------------------------------------
__global__ void __launch_bounds__(128, 4) gemm_tc(const float* __restrict__ w,
                                                  const float* __restrict__ x) {
    __shared__ __align__(128) uint8_t A_HI[2][128 * 64];
    __shared__ __align__(128) uint8_t A_LO[2][128 * 64];
    __shared__ __align__(128) uint8_t B_HI[2][32 * 64];
    __shared__ __align__(128) uint8_t B_LO[2][32 * 64];

    const int mt   = blockIdx.x;
    const int ks   = blockIdx.y;
    const int tid  = threadIdx.x;
    const int wid  = tid >> 5;
    const int lane = tid & 31;

    const int o = mt * 4 + wid;      // A-convert: row m = tid = (o_local, u)
    const int u = lane;
    const int m = tid;

    const int xb = tid >> 2, xq = tid & 3;   // B-convert mapping

    const float* const wbase =
        w + (((size_t)(ks * NCH * 2) * OO + o) * CC) * UU + u;
    const float4* const xbase =
        (const float4*)(x + (size_t)xb * KTOT + ks * (NCH * KC)) + xq * 2;

    float  va[32];
    float4 vb[2];

    // prefetch chunk 0
#pragma unroll
    for (int e = 0; e < 32; e++)
        va[e] = wbase[(size_t)(e >> 4) * ISTRIDE + (e & 15) * UU];
    vb[0] = xbase[0];
    vb[1] = xbase[1];

    float acc[2][4][4];
#pragma unroll
    for (int a = 0; a < 2; a++)
#pragma unroll
        for (int b = 0; b < 4; b++)
#pragma unroll
            for (int c = 0; c < 4; c++) acc[a][b][c] = 0.f;

    for (int t = 0; t < NCH; t++) {
        const int p = t & 1;

        // ---- convert & store chunk t (consumes va/vb)
#pragma unroll
        for (int j = 0; j < 4; j++) {        // 4 groups of 8 k's
            uint32_t h[4], l[4];
#pragma unroll
            for (int q = 0; q < 4; q++) {
                float v0 = va[8 * j + 2 * q], v1 = va[8 * j + 2 * q + 1];
                h[q] = pack_bf16(v0, v1);
                float r0 = v0 - __uint_as_float(h[q] << 16);
                float r1 = v1 - __uint_as_float(h[q] & 0xffff0000u);
                l[q] = pack_bf16(r0, r1);
            }
            const uint32_t off = sw64(m, j);
            *(uint4*)(A_HI[p] + off) = make_uint4(h[0], h[1], h[2], h[3]);
            *(uint4*)(A_LO[p] + off) = make_uint4(l[0], l[1], l[2], l[3]);
        }
        {   // B: thread's 8 floats = k group xq of row xb
            float v[8] = {vb[0].x, vb[0].y, vb[0].z, vb[0].w,
                          vb[1].x, vb[1].y, vb[1].z, vb[1].w};
            uint32_t h[4], l[4];
#pragma unroll
            for (int q = 0; q < 4; q++) {
                h[q] = pack_bf16(v[2 * q], v[2 * q + 1]);
                float r0 = v[2 * q]     - __uint_as_float(h[q] << 16);
                float r1 = v[2 * q + 1] - __uint_as_float(h[q] & 0xffff0000u);
                l[q] = pack_bf16(r0, r1);
            }
            const uint32_t off = sw64(xb, xq);
            *(uint4*)(B_HI[p] + off) = make_uint4(h[0], h[1], h[2], h[3]);
            *(uint4*)(B_LO[p] + off) = make_uint4(l[0], l[1], l[2], l[3]);
        }

        // ---- prefetch chunk t+1 BEFORE barrier: LDG overlaps bar wait + MMA
        if (t + 1 < NCH) {
            const float* wp = wbase + (size_t)((t + 1) * 2) * ISTRIDE;
#pragma unroll
            for (int e = 0; e < 32; e++)
                va[e] = wp[(size_t)(e >> 4) * ISTRIDE + (e & 15) * UU];
            const float4* xp = xbase + (t + 1) * (KC / 4);
            vb[0] = xp[0];
            vb[1] = xp[1];
        }

        __syncthreads();   // buf[p] ready for all warps

        // ---- MMA: 2 k-tiles of 16
        const uint32_t aHi = smem_u32(A_HI[p]), aLo = smem_u32(A_LO[p]);
        const uint32_t bHi = smem_u32(B_HI[p]), bLo = smem_u32(B_LO[p]);
#pragma unroll
        for (int kt = 0; kt < 2; kt++) {
            uint32_t ahi[2][4], alo[2][4], bhiR[2][4], bloR[2][4];

            const int ar  = (lane & 7) + ((lane >> 3) & 1) * 8;
            const int akg = 2 * kt + (lane >> 4);
#pragma unroll
            for (int m2 = 0; m2 < 2; m2++) {
                const int row = wid * 32 + m2 * 16 + ar;
                const uint32_t off = sw64(row, akg);
                ldsm_x4(ahi[m2], aHi + off);
                ldsm_x4(alo[m2], aLo + off);
            }
            const int bn  = (lane & 7) + ((lane >> 4) & 1) * 8;
            const int bkg = 2 * kt + ((lane >> 3) & 1);
#pragma unroll
            for (int g2 = 0; g2 < 2; g2++) {
                const int n = g2 * 16 + bn;
                const uint32_t off = sw64(n, bkg);
                ldsm_x4(bhiR[g2], bHi + off);
                ldsm_x4(bloR[g2], bLo + off);
            }
#pragma unroll
            for (int m2 = 0; m2 < 2; m2++)
#pragma unroll
                for (int nt = 0; nt < 4; nt++) {
                    const uint32_t bh0 = bhiR[nt >> 1][(nt & 1) * 2];
                    const uint32_t bh1 = bhiR[nt >> 1][(nt & 1) * 2 + 1];
                    const uint32_t bl0 = bloR[nt >> 1][(nt & 1) * 2];
                    const uint32_t bl1 = bloR[nt >> 1][(nt & 1) * 2 + 1];
                    mma_bf16(acc[m2][nt], ahi[m2], bh0, bh1);
                    mma_bf16(acc[m2][nt], alo[m2], bh0, bh1);
                    mma_bf16(acc[m2][nt], ahi[m2], bl0, bl1);
                }
        }
        // buf[p] rewritten only at t+2, after every warp passed sync(t+1).
    }

    // ---- epilogue: D fragments -> g_spart[(mt*KS+ks)][m_local][b]
    float* outp = g_spart + ((size_t)(mt * KS + ks)) * (128 * BB);
#pragma unroll
    for (int m2 = 0; m2 < 2; m2++)
#pragma unroll
        for (int nt = 0; nt < 4; nt++) {
            const int r0 = wid * 32 + m2 * 16 + (lane >> 2);
            const int c  = nt * 8 + 2 * (lane & 3);
            *(float2*)(outp + (size_t)r0 * BB + c) =
                make_float2(acc[m2][nt][0], acc[m2][nt][1]);
            *(float2*)(outp + (size_t)(r0 + 8) * BB + c) =
                make_float2(acc[m2][nt][2], acc[m2][nt][3]);
        }
}

// ---------------------------------------------------------------------------
// Fused reduce + squash: grid (OO, 4), 256 threads. Block = (o, 8 b's).
// Partials are L2-resident (8MB just written). One pass, no intermediate.
// ---------------------------------------------------------------------------
__global__ void __launch_bounds__(256) reduce_squash(float* __restrict__ out) {
    const int o  = blockIdx.x;
    const int b0 = blockIdx.y * 8;
    const int t  = threadIdx.x;
    const int mt = o >> 2;

    __shared__ float4 smq[4][32][2];   // [kp][u][q]
    __shared__ float fin[32][9];       // [u][b-sub], pad 9
    __shared__ float scale_s[8];

    {   // phase 1: thread (q = t&1, u = (t>>1)&31, kp = t>>6) sums 16 ks
        const int q  = t & 1;
        const int uu = (t >> 1) & 31;
        const int kp = t >> 6;
        const int mrow = (o & 3) * 32 + uu;
        const float4* p = (const float4*)(g_spart +
            (((size_t)mt * KS + kp * 16) * 128 + mrow) * BB + b0) + q;
        float4 s = make_float4(0.f, 0.f, 0.f, 0.f);
#pragma unroll
        for (int j = 0; j < 16; j++) {
            float4 v = p[(size_t)j * (128 * BB / 4)];
            s.x += v.x; s.y += v.y; s.z += v.z; s.w += v.w;
        }
        smq[kp][uu][q] = s;
    }
    __syncthreads();

    {   // phase 2: thread (u2 = t>>3, bb = t&7) folds the 4 kp partials
        const int u2 = t >> 3, bb = t & 7;
        float r = 0.f;
#pragma unroll
        for (int kp = 0; kp < 4; kp++) {
            float4 v = smq[kp][u2][bb >> 2];
            r += (&v.x)[bb & 3];
        }
        fin[u2][bb] = r;
    }
    __syncthreads();

    if (t < 8) {   // phase 3: per-b norm & scale
        float nsq = 0.f;
#pragma unroll
        for (int uv = 0; uv < UU; uv++) {
            float sv = fin[uv][t];
            nsq += sv * sv;
        }
        scale_s[t] = sqrtf(nsq) / (1.0f + nsq);
    }
    __syncthreads();

    {   // phase 4: coalesced output rows (32 consecutive u per warp)
        const int u3 = t & 31, bb3 = t >> 5;
        out[(size_t)(b0 + bb3) * (OO * UU) + o * UU + u3] =
            fin[u3][bb3] * scale_s[bb3];
    }
}

// ---------------------------------------------------------------------------
extern "C" void kernel_launch(void* const* d_in, const int* in_sizes, int n_in,
                              void* d_out, int out_size) {
    const float* x = (const float*)d_in[0];
    const float* w = (const float*)d_in[1];
    if (n_in >= 2 && in_sizes[0] > in_sizes[1]) {   // guard input ordering
        x = (const float*)d_in[1];
        w = (const float*)d_in[0];
    }

    gemm_tc<<<dim3(MT, KS), 128>>>(w, x);
    reduce_squash<<<dim3(OO, 4), 256>>>((float*)d_out);
}